// round 5
// baseline (speedup 1.0000x reference)
#include <cuda_runtime.h>
#include <cuda_bf16.h>
#include <math.h>

// Problem constants
#define B_   4
#define S_   2048
#define DE_  1024
#define NH_  16
#define DH_  64
#define MROWS (B_ * S_)          // 8192
#define N_QKV (3 * DE_)          // 3072

// Scratch (allocation-free rule: __device__ globals)
__device__ float g_qkv[(size_t)MROWS * N_QKV];   // [8192, 3072]
__device__ float g_att[(size_t)MROWS * DE_];     // [8192, 1024]

// ---------------------------------------------------------------------------
// GEMM: C[M,N] = A[M,K] @ W[N,K]^T + bias[N]
// BM=BN=128, BK=16, 256 threads, 8x8 micro-tile (split-64 layout for
// conflict-free LDS.128).
// ---------------------------------------------------------------------------
#define BM 128
#define BN 128
#define BK 16
#define PAD 4

__global__ __launch_bounds__(256) void gemm_bias_kernel(
    const float* __restrict__ A, const float* __restrict__ W,
    const float* __restrict__ bias, float* __restrict__ C,
    int M, int N, int K)
{
    __shared__ float As[BK][BM + PAD];
    __shared__ float Ws[BK][BN + PAD];

    const int tid = threadIdx.x;
    const int tx = tid & 15;       // 0..15 -> N micro position
    const int ty = tid >> 4;       // 0..15 -> M micro position
    const int bm = blockIdx.y * BM;
    const int bn = blockIdx.x * BN;

    // load mapping: each thread loads 2 float4 per operand per k-tile
    const int lrow = tid >> 1;            // 0..127
    const int lcb  = (tid & 1) * 2;       // 0 or 2 (chunk base)

    float acc[2][2][4][4];
    #pragma unroll
    for (int a = 0; a < 2; a++)
        #pragma unroll
        for (int b = 0; b < 2; b++)
            #pragma unroll
            for (int i = 0; i < 4; i++)
                #pragma unroll
                for (int j = 0; j < 4; j++) acc[a][b][i][j] = 0.f;

    const float* Arow = A + (size_t)(bm + lrow) * K;
    const float* Wrow = W + (size_t)(bn + lrow) * K;

    for (int k0 = 0; k0 < K; k0 += BK) {
        #pragma unroll
        for (int u = 0; u < 2; u++) {
            const int kc = (lcb + u) * 4;             // 0,4,8,12
            float4 av = *reinterpret_cast<const float4*>(Arow + k0 + kc);
            float4 wv = *reinterpret_cast<const float4*>(Wrow + k0 + kc);
            As[kc + 0][lrow] = av.x; As[kc + 1][lrow] = av.y;
            As[kc + 2][lrow] = av.z; As[kc + 3][lrow] = av.w;
            Ws[kc + 0][lrow] = wv.x; Ws[kc + 1][lrow] = wv.y;
            Ws[kc + 2][lrow] = wv.z; Ws[kc + 3][lrow] = wv.w;
        }
        __syncthreads();

        #pragma unroll
        for (int kk = 0; kk < BK; kk++) {
            float4 a0 = *reinterpret_cast<const float4*>(&As[kk][ty * 4]);
            float4 a1 = *reinterpret_cast<const float4*>(&As[kk][64 + ty * 4]);
            float4 w0 = *reinterpret_cast<const float4*>(&Ws[kk][tx * 4]);
            float4 w1 = *reinterpret_cast<const float4*>(&Ws[kk][64 + tx * 4]);
            float af[2][4] = {{a0.x, a0.y, a0.z, a0.w}, {a1.x, a1.y, a1.z, a1.w}};
            float wf[2][4] = {{w0.x, w0.y, w0.z, w0.w}, {w1.x, w1.y, w1.z, w1.w}};
            #pragma unroll
            for (int ri = 0; ri < 2; ri++)
                #pragma unroll
                for (int cj = 0; cj < 2; cj++)
                    #pragma unroll
                    for (int i = 0; i < 4; i++)
                        #pragma unroll
                        for (int j = 0; j < 4; j++)
                            acc[ri][cj][i][j] += af[ri][i] * wf[cj][j];
        }
        __syncthreads();
    }

    // bias (cached)
    float bv[2][4];
    #pragma unroll
    for (int cj = 0; cj < 2; cj++) {
        float4 b4 = *reinterpret_cast<const float4*>(&bias[bn + cj * 64 + tx * 4]);
        bv[cj][0] = b4.x; bv[cj][1] = b4.y; bv[cj][2] = b4.z; bv[cj][3] = b4.w;
    }

    #pragma unroll
    for (int ri = 0; ri < 2; ri++) {
        #pragma unroll
        for (int i = 0; i < 4; i++) {
            const int r = bm + ri * 64 + ty * 4 + i;
            float* crow = C + (size_t)r * N + bn;
            #pragma unroll
            for (int cj = 0; cj < 2; cj++) {
                float4 o;
                o.x = acc[ri][cj][i][0] + bv[cj][0];
                o.y = acc[ri][cj][i][1] + bv[cj][1];
                o.z = acc[ri][cj][i][2] + bv[cj][2];
                o.w = acc[ri][cj][i][3] + bv[cj][3];
                *reinterpret_cast<float4*>(&crow[cj * 64 + tx * 4]) = o;
            }
        }
    }
}

// ---------------------------------------------------------------------------
// Flash attention (causal), fp32. 64x64 tiles, 256 threads, 4x4 micro-tiles.
// qkv layout: [b, s, 3*1024]; out layout: [b*s, 1024] with head h at col h*64.
// ---------------------------------------------------------------------------
#define AQ 64
#define AK 64
// dynamic smem: Qs[64][68] Ks[64][68] Vs[64][64] Ps[64][68] + 3*64 stats
#define ATTN_SMEM_FLOATS (64*68*3 + 64*64 + 3*64)
#define ATTN_SMEM_BYTES  (ATTN_SMEM_FLOATS * 4)

__global__ __launch_bounds__(256) void attn_kernel(
    const float* __restrict__ qkv, float* __restrict__ out)
{
    extern __shared__ float sm[];
    float (*Qs)[68] = reinterpret_cast<float(*)[68]>(sm);                 // [64][68] (transposed: [d][i])
    float (*Ks)[68] = reinterpret_cast<float(*)[68]>(sm + 64 * 68);       // [64][68] (transposed: [d][j])
    float (*Vs)[64] = reinterpret_cast<float(*)[64]>(sm + 2 * 64 * 68);   // [64][64] ([j][d])
    float (*Ps)[68] = reinterpret_cast<float(*)[68]>(sm + 2 * 64 * 68 + 64 * 64); // [64][68]
    float* m_s  = sm + 2 * 64 * 68 + 64 * 64 + 64 * 68;
    float* l_s  = m_s + 64;
    float* rs_s = l_s + 64;

    const int STR = 3 * DE_;
    const int qt = blockIdx.x;
    const int h  = blockIdx.y;
    const int b  = blockIdx.z;

    const float* Qg = qkv + (size_t)b * S_ * STR + h * DH_;
    const float* Kg = Qg + DE_;
    const float* Vg = Qg + 2 * DE_;

    const int tid = threadIdx.x;
    const int tx = tid & 15, ty = tid >> 4;
    const int lrow = tid >> 2;         // 0..63
    const int lchunk = tid & 3;        // 0..3

    // Load Q tile transposed: Qs[d][i]
    {
        const float* qrow = Qg + (size_t)(qt * AQ + lrow) * STR;
        #pragma unroll
        for (int u = 0; u < 4; u++) {
            const int d = (lchunk * 4 + u) * 4;
            float4 v = *reinterpret_cast<const float4*>(qrow + d);
            Qs[d + 0][lrow] = v.x; Qs[d + 1][lrow] = v.y;
            Qs[d + 2][lrow] = v.z; Qs[d + 3][lrow] = v.w;
        }
    }
    if (tid < 64) { m_s[tid] = -INFINITY; l_s[tid] = 0.f; }

    float oacc[4][4] = {};
    const float scale = 0.125f;  // 1/sqrt(64)

    for (int kt = 0; kt <= qt; kt++) {
        __syncthreads();   // Q visible (1st iter); prior-iter Ps/Vs reads done

        // Load K (transposed) and V tiles
        {
            const float* krow = Kg + (size_t)(kt * AK + lrow) * STR;
            const float* vrow = Vg + (size_t)(kt * AK + lrow) * STR;
            #pragma unroll
            for (int u = 0; u < 4; u++) {
                const int d = (lchunk * 4 + u) * 4;
                float4 kv = *reinterpret_cast<const float4*>(krow + d);
                Ks[d + 0][lrow] = kv.x; Ks[d + 1][lrow] = kv.y;
                Ks[d + 2][lrow] = kv.z; Ks[d + 3][lrow] = kv.w;
                *reinterpret_cast<float4*>(&Vs[lrow][d]) =
                    *reinterpret_cast<const float4*>(vrow + d);
            }
        }
        __syncthreads();

        // S = scale * Q K^T  (4x4 per thread)
        float sacc[4][4] = {};
        #pragma unroll
        for (int d = 0; d < DH_; d++) {
            float4 a = *reinterpret_cast<const float4*>(&Qs[d][ty * 4]);
            float4 w = *reinterpret_cast<const float4*>(&Ks[d][tx * 4]);
            float af[4] = {a.x, a.y, a.z, a.w};
            float wf[4] = {w.x, w.y, w.z, w.w};
            #pragma unroll
            for (int i = 0; i < 4; i++)
                #pragma unroll
                for (int j = 0; j < 4; j++) sacc[i][j] += af[i] * wf[j];
        }
        const bool diag = (kt == qt);
        #pragma unroll
        for (int i = 0; i < 4; i++)
            #pragma unroll
            for (int j = 0; j < 4; j++) {
                float s = sacc[i][j] * scale;
                if (diag && (tx * 4 + j) > (ty * 4 + i)) s = -INFINITY;
                Ps[ty * 4 + i][tx * 4 + j] = s;
            }
        __syncthreads();

        // Row stats (4 threads per row; shfl within 4-lane groups)
        {
            const int r = tid >> 2, q = tid & 3;
            float mx = -INFINITY;
            #pragma unroll
            for (int j = 0; j < 16; j++) mx = fmaxf(mx, Ps[r][q * 16 + j]);
            mx = fmaxf(mx, __shfl_xor_sync(0xffffffffu, mx, 1));
            mx = fmaxf(mx, __shfl_xor_sync(0xffffffffu, mx, 2));
            const float m_old = m_s[r];
            const float m_new = fmaxf(m_old, mx);
            float sum = 0.f;
            #pragma unroll
            for (int j = 0; j < 16; j++) {
                float p = __expf(Ps[r][q * 16 + j] - m_new);
                Ps[r][q * 16 + j] = p;
                sum += p;
            }
            sum += __shfl_xor_sync(0xffffffffu, sum, 1);
            sum += __shfl_xor_sync(0xffffffffu, sum, 2);
            if (q == 0) {
                const float rs = __expf(m_old - m_new);
                m_s[r] = m_new;
                l_s[r] = l_s[r] * rs + sum;
                rs_s[r] = rs;
            }
        }
        __syncthreads();

        // Rescale + O += P V
        #pragma unroll
        for (int i = 0; i < 4; i++) {
            const float rs = rs_s[ty * 4 + i];
            #pragma unroll
            for (int j = 0; j < 4; j++) oacc[i][j] *= rs;
        }
        #pragma unroll
        for (int jj = 0; jj < AK; jj++) {
            float4 w = *reinterpret_cast<const float4*>(&Vs[jj][tx * 4]);
            float wf[4] = {w.x, w.y, w.z, w.w};
            float pf[4];
            #pragma unroll
            for (int i = 0; i < 4; i++) pf[i] = Ps[ty * 4 + i][jj];
            #pragma unroll
            for (int i = 0; i < 4; i++)
                #pragma unroll
                for (int j = 0; j < 4; j++) oacc[i][j] += pf[i] * wf[j];
        }
    }

    // Epilogue: divide by l, write to [b*s, 1024] at head column h*64
    #pragma unroll
    for (int i = 0; i < 4; i++) {
        const float inv = 1.f / l_s[ty * 4 + i];
        float* orow = out + ((size_t)b * S_ + (size_t)qt * AQ + ty * 4 + i) * DE_ + h * DH_;
        float4 o;
        o.x = oacc[i][0] * inv; o.y = oacc[i][1] * inv;
        o.z = oacc[i][2] * inv; o.w = oacc[i][3] * inv;
        *reinterpret_cast<float4*>(&orow[tx * 4]) = o;
    }
}

// ---------------------------------------------------------------------------
extern "C" void kernel_launch(void* const* d_in, const int* in_sizes, int n_in,
                              void* d_out, int out_size)
{
    const float* x     = (const float*)d_in[0];
    const float* W_in  = (const float*)d_in[1];
    const float* b_in  = (const float*)d_in[2];
    const float* W_out = (const float*)d_in[3];
    const float* b_out = (const float*)d_in[4];
    float* out = (float*)d_out;

    float* qkv = nullptr;
    float* att = nullptr;
    cudaGetSymbolAddress((void**)&qkv, g_qkv);
    cudaGetSymbolAddress((void**)&att, g_att);

    cudaFuncSetAttribute(attn_kernel,
                         cudaFuncAttributeMaxDynamicSharedMemorySize,
                         ATTN_SMEM_BYTES);

    // 1) QKV projection: [8192,3072] = x @ W_in^T + b_in
    {
        dim3 grid(N_QKV / BN, MROWS / BM);
        gemm_bias_kernel<<<grid, 256>>>(x, W_in, b_in, qkv, MROWS, N_QKV, DE_);
    }
    // 2) Causal flash attention -> att [8192,1024]
    {
        dim3 grid(S_ / AQ, NH_, B_);
        attn_kernel<<<grid, 256, ATTN_SMEM_BYTES>>>(qkv, att);
    }
    // 3) Output projection: out = att @ W_out^T + b_out
    {
        dim3 grid(DE_ / BN, MROWS / BM);
        gemm_bias_kernel<<<grid, 256>>>(att, W_out, b_out, out, MROWS, DE_, DE_);
    }
}

// round 8
// speedup vs baseline: 1.3681x; 1.3681x over previous
#include <cuda_runtime.h>
#include <cuda_bf16.h>
#include <math.h>
#include <stdint.h>

// Problem constants
#define B_   4
#define S_   2048
#define DE_  1024
#define NH_  16
#define DH_  64
#define MROWS (B_ * S_)          // 8192
#define N_QKV (3 * DE_)          // 3072

// Scratch (allocation-free rule: __device__ globals)
__device__ float g_qkv[(size_t)MROWS * N_QKV];   // [8192, 3072]
__device__ float g_att[(size_t)MROWS * DE_];     // [8192, 1024]

// ===========================================================================
// mma.sync helpers (plain PTX, sm_80+ -> HMMA on sm_103)
// ===========================================================================
__device__ __forceinline__ void mma16816(float* d, const uint32_t* a, const uint32_t* b)
{
    asm volatile(
        "mma.sync.aligned.m16n8k16.row.col.f32.bf16.bf16.f32 "
        "{%0,%1,%2,%3}, {%4,%5,%6,%7}, {%8,%9}, {%0,%1,%2,%3};"
        : "+f"(d[0]), "+f"(d[1]), "+f"(d[2]), "+f"(d[3])
        : "r"(a[0]), "r"(a[1]), "r"(a[2]), "r"(a[3]), "r"(b[0]), "r"(b[1]));
}

// pack two fp32 -> bf16x2 (x0 in low half)
__device__ __forceinline__ uint32_t pack_bf16x2(float x0, float x1)
{
    uint32_t r;
    asm("cvt.rn.bf16x2.f32 %0, %1, %2;" : "=r"(r) : "f"(x1), "f"(x0));
    return r;
}

// ===========================================================================
// GEMM: C[M,N] = A[M,K] @ W[N,K]^T + bias[N], fp32 via bf16-split mma.sync.
// CTA 128x128, BK=32, 256 threads = 8 warps as 2(M) x 4(N); warp tile 64x32.
// SMEM row stride = 40 bf16 (20 words) -> conflict-free fragment LDS.
// ===========================================================================
#define WS 20          // word (b32) stride per SMEM row (= 40 bf16)
#define GBM 128
#define GBN 128
#define GBK 32

__global__ __launch_bounds__(256, 2) void gemm_mma_kernel(
    const float* __restrict__ A, const float* __restrict__ W,
    const float* __restrict__ bias, float* __restrict__ C,
    int M, int N, int K)
{
    __shared__ uint32_t sAh[128 * WS], sAl[128 * WS];
    __shared__ uint32_t sWh[128 * WS], sWl[128 * WS];   // 4 * 10240B = 40KB

    const int tid  = threadIdx.x;
    const int lane = tid & 31;
    const int wid  = tid >> 5;
    const int wm   = wid >> 2;          // 0..1  (64 M-rows each)
    const int wn   = wid & 3;           // 0..3  (32 N-cols each)
    const int bm   = blockIdx.y * GBM;
    const int bn   = blockIdx.x * GBN;

    float acc[4][4][4];
    #pragma unroll
    for (int mi = 0; mi < 4; mi++)
        #pragma unroll
        for (int ni = 0; ni < 4; ni++)
            #pragma unroll
            for (int e = 0; e < 4; e++) acc[mi][ni][e] = 0.f;

    // gmem load mapping: thread -> (row = tid>>1, k-half = tid&1), 16 floats
    const int lrow = tid >> 1;
    const int lh   = tid & 1;
    const float* Ap = A + (size_t)(bm + lrow) * K + lh * 16;
    const float* Wp = W + (size_t)(bn + lrow) * K + lh * 16;
    const int sw = lrow * WS + lh * 8;   // word base for this thread's stores

    // fragment addressing (constant per thread)
    const int fr = lane >> 2;       // 0..7
    const int fc = lane & 3;        // 0..3

    for (int k0 = 0; k0 < K; k0 += GBK) {
        // ---- global loads (issued before sync so latency overlaps wait) ----
        float av[16], wv[16];
        #pragma unroll
        for (int i = 0; i < 4; i++) {
            *reinterpret_cast<float4*>(&av[4 * i]) =
                *reinterpret_cast<const float4*>(Ap + k0 + 4 * i);
            *reinterpret_cast<float4*>(&wv[4 * i]) =
                *reinterpret_cast<const float4*>(Wp + k0 + 4 * i);
        }

        __syncthreads();   // previous iteration's fragment reads complete

        // ---- split to bf16 hi/lo and store (2x STS.128 per matrix) ----
        {
            uint32_t ah[8], al[8], wh[8], wl[8];
            #pragma unroll
            for (int p = 0; p < 8; p++) {
                float x0 = av[2 * p], x1 = av[2 * p + 1];
                uint32_t hp = pack_bf16x2(x0, x1);
                float h0 = __uint_as_float(hp << 16);
                float h1 = __uint_as_float(hp & 0xffff0000u);
                ah[p] = hp;
                al[p] = pack_bf16x2(x0 - h0, x1 - h1);

                float y0 = wv[2 * p], y1 = wv[2 * p + 1];
                uint32_t hq = pack_bf16x2(y0, y1);
                float g0 = __uint_as_float(hq << 16);
                float g1 = __uint_as_float(hq & 0xffff0000u);
                wh[p] = hq;
                wl[p] = pack_bf16x2(y0 - g0, y1 - g1);
            }
            *reinterpret_cast<uint4*>(&sAh[sw])     = make_uint4(ah[0], ah[1], ah[2], ah[3]);
            *reinterpret_cast<uint4*>(&sAh[sw + 4]) = make_uint4(ah[4], ah[5], ah[6], ah[7]);
            *reinterpret_cast<uint4*>(&sAl[sw])     = make_uint4(al[0], al[1], al[2], al[3]);
            *reinterpret_cast<uint4*>(&sAl[sw + 4]) = make_uint4(al[4], al[5], al[6], al[7]);
            *reinterpret_cast<uint4*>(&sWh[sw])     = make_uint4(wh[0], wh[1], wh[2], wh[3]);
            *reinterpret_cast<uint4*>(&sWh[sw + 4]) = make_uint4(wh[4], wh[5], wh[6], wh[7]);
            *reinterpret_cast<uint4*>(&sWl[sw])     = make_uint4(wl[0], wl[1], wl[2], wl[3]);
            *reinterpret_cast<uint4*>(&sWl[sw + 4]) = make_uint4(wl[4], wl[5], wl[6], wl[7]);
        }
        __syncthreads();

        // ---- 2 k16 steps x 3 split terms ----
        #pragma unroll
        for (int s = 0; s < 2; s++) {
            const int wb = s * 8;
            uint32_t af[4][4], bh[4][2], bl[4][2];

            // B fragments (hi and lo) — resident for all 3 terms
            #pragma unroll
            for (int ni = 0; ni < 4; ni++) {
                const int nb = (wn * 32 + ni * 8 + fr) * WS + wb + fc;
                bh[ni][0] = sWh[nb]; bh[ni][1] = sWh[nb + 4];
                bl[ni][0] = sWl[nb]; bl[ni][1] = sWl[nb + 4];
            }
            // A hi fragments
            #pragma unroll
            for (int mi = 0; mi < 4; mi++) {
                const int ab = (wm * 64 + mi * 16 + fr) * WS + wb + fc;
                af[mi][0] = sAh[ab];           af[mi][1] = sAh[ab + 8 * WS];
                af[mi][2] = sAh[ab + 4];       af[mi][3] = sAh[ab + 8 * WS + 4];
            }
            // Ah*Wh and Ah*Wl
            #pragma unroll
            for (int mi = 0; mi < 4; mi++)
                #pragma unroll
                for (int ni = 0; ni < 4; ni++) {
                    mma16816(acc[mi][ni], af[mi], bh[ni]);
                    mma16816(acc[mi][ni], af[mi], bl[ni]);
                }
            // A lo fragments (overwrite)
            #pragma unroll
            for (int mi = 0; mi < 4; mi++) {
                const int ab = (wm * 64 + mi * 16 + fr) * WS + wb + fc;
                af[mi][0] = sAl[ab];           af[mi][1] = sAl[ab + 8 * WS];
                af[mi][2] = sAl[ab + 4];       af[mi][3] = sAl[ab + 8 * WS + 4];
            }
            // Al*Wh
            #pragma unroll
            for (int mi = 0; mi < 4; mi++)
                #pragma unroll
                for (int ni = 0; ni < 4; ni++)
                    mma16816(acc[mi][ni], af[mi], bh[ni]);
        }
    }

    // ---- epilogue: acc + bias -> C (float2 stores) ----
    #pragma unroll
    for (int ni = 0; ni < 4; ni++) {
        const int col = bn + wn * 32 + ni * 8 + fc * 2;
        const float2 bv = *reinterpret_cast<const float2*>(&bias[col]);
        #pragma unroll
        for (int mi = 0; mi < 4; mi++) {
            const int row = bm + wm * 64 + mi * 16 + fr;
            float2 o0, o1;
            o0.x = acc[mi][ni][0] + bv.x; o0.y = acc[mi][ni][1] + bv.y;
            o1.x = acc[mi][ni][2] + bv.x; o1.y = acc[mi][ni][3] + bv.y;
            *reinterpret_cast<float2*>(C + (size_t)row * N + col)       = o0;
            *reinterpret_cast<float2*>(C + (size_t)(row + 8) * N + col) = o1;
        }
    }
}

// ---------------------------------------------------------------------------
// Flash attention (causal), fp32. 64x64 tiles, 256 threads, 4x4 micro-tiles.
// qkv layout: [b, s, 3*1024]; out layout: [b*s, 1024] with head h at col h*64.
// ---------------------------------------------------------------------------
#define AQ 64
#define AK 64
#define ATTN_SMEM_FLOATS (64*68*3 + 64*64 + 3*64)
#define ATTN_SMEM_BYTES  (ATTN_SMEM_FLOATS * 4)

__global__ __launch_bounds__(256) void attn_kernel(
    const float* __restrict__ qkv, float* __restrict__ out)
{
    extern __shared__ float sm[];
    float (*Qs)[68] = reinterpret_cast<float(*)[68]>(sm);
    float (*Ks)[68] = reinterpret_cast<float(*)[68]>(sm + 64 * 68);
    float (*Vs)[64] = reinterpret_cast<float(*)[64]>(sm + 2 * 64 * 68);
    float (*Ps)[68] = reinterpret_cast<float(*)[68]>(sm + 2 * 64 * 68 + 64 * 64);
    float* m_s  = sm + 2 * 64 * 68 + 64 * 64 + 64 * 68;
    float* l_s  = m_s + 64;
    float* rs_s = l_s + 64;

    const int STR = 3 * DE_;
    const int qt = blockIdx.x;
    const int h  = blockIdx.y;
    const int b  = blockIdx.z;

    const float* Qg = qkv + (size_t)b * S_ * STR + h * DH_;
    const float* Kg = Qg + DE_;
    const float* Vg = Qg + 2 * DE_;

    const int tid = threadIdx.x;
    const int tx = tid & 15, ty = tid >> 4;
    const int lrow = tid >> 2;
    const int lchunk = tid & 3;

    {
        const float* qrow = Qg + (size_t)(qt * AQ + lrow) * STR;
        #pragma unroll
        for (int u = 0; u < 4; u++) {
            const int d = (lchunk * 4 + u) * 4;
            float4 v = *reinterpret_cast<const float4*>(qrow + d);
            Qs[d + 0][lrow] = v.x; Qs[d + 1][lrow] = v.y;
            Qs[d + 2][lrow] = v.z; Qs[d + 3][lrow] = v.w;
        }
    }
    if (tid < 64) { m_s[tid] = -INFINITY; l_s[tid] = 0.f; }

    float oacc[4][4] = {};
    const float scale = 0.125f;

    for (int kt = 0; kt <= qt; kt++) {
        __syncthreads();

        {
            const float* krow = Kg + (size_t)(kt * AK + lrow) * STR;
            const float* vrow = Vg + (size_t)(kt * AK + lrow) * STR;
            #pragma unroll
            for (int u = 0; u < 4; u++) {
                const int d = (lchunk * 4 + u) * 4;
                float4 kv = *reinterpret_cast<const float4*>(krow + d);
                Ks[d + 0][lrow] = kv.x; Ks[d + 1][lrow] = kv.y;
                Ks[d + 2][lrow] = kv.z; Ks[d + 3][lrow] = kv.w;
                *reinterpret_cast<float4*>(&Vs[lrow][d]) =
                    *reinterpret_cast<const float4*>(vrow + d);
            }
        }
        __syncthreads();

        float sacc[4][4] = {};
        #pragma unroll
        for (int d = 0; d < DH_; d++) {
            float4 a = *reinterpret_cast<const float4*>(&Qs[d][ty * 4]);
            float4 w = *reinterpret_cast<const float4*>(&Ks[d][tx * 4]);
            float af[4] = {a.x, a.y, a.z, a.w};
            float wf[4] = {w.x, w.y, w.z, w.w};
            #pragma unroll
            for (int i = 0; i < 4; i++)
                #pragma unroll
                for (int j = 0; j < 4; j++) sacc[i][j] += af[i] * wf[j];
        }
        const bool diag = (kt == qt);
        #pragma unroll
        for (int i = 0; i < 4; i++)
            #pragma unroll
            for (int j = 0; j < 4; j++) {
                float s = sacc[i][j] * scale;
                if (diag && (tx * 4 + j) > (ty * 4 + i)) s = -INFINITY;
                Ps[ty * 4 + i][tx * 4 + j] = s;
            }
        __syncthreads();

        {
            const int rr = tid >> 2, q = tid & 3;
            float mx = -INFINITY;
            #pragma unroll
            for (int j = 0; j < 16; j++) mx = fmaxf(mx, Ps[rr][q * 16 + j]);
            mx = fmaxf(mx, __shfl_xor_sync(0xffffffffu, mx, 1));
            mx = fmaxf(mx, __shfl_xor_sync(0xffffffffu, mx, 2));
            const float m_old = m_s[rr];
            const float m_new = fmaxf(m_old, mx);
            float sum = 0.f;
            #pragma unroll
            for (int j = 0; j < 16; j++) {
                float p = __expf(Ps[rr][q * 16 + j] - m_new);
                Ps[rr][q * 16 + j] = p;
                sum += p;
            }
            sum += __shfl_xor_sync(0xffffffffu, sum, 1);
            sum += __shfl_xor_sync(0xffffffffu, sum, 2);
            if (q == 0) {
                const float rs = __expf(m_old - m_new);
                m_s[rr] = m_new;
                l_s[rr] = l_s[rr] * rs + sum;
                rs_s[rr] = rs;
            }
        }
        __syncthreads();

        #pragma unroll
        for (int i = 0; i < 4; i++) {
            const float rs = rs_s[ty * 4 + i];
            #pragma unroll
            for (int j = 0; j < 4; j++) oacc[i][j] *= rs;
        }
        #pragma unroll
        for (int jj = 0; jj < AK; jj++) {
            float4 w = *reinterpret_cast<const float4*>(&Vs[jj][tx * 4]);
            float wf[4] = {w.x, w.y, w.z, w.w};
            float pf[4];
            #pragma unroll
            for (int i = 0; i < 4; i++) pf[i] = Ps[ty * 4 + i][jj];
            #pragma unroll
            for (int i = 0; i < 4; i++)
                #pragma unroll
                for (int j = 0; j < 4; j++) oacc[i][j] += pf[i] * wf[j];
        }
    }

    #pragma unroll
    for (int i = 0; i < 4; i++) {
        const float inv = 1.f / l_s[ty * 4 + i];
        float* orow = out + ((size_t)b * S_ + (size_t)qt * AQ + ty * 4 + i) * DE_ + h * DH_;
        float4 o;
        o.x = oacc[i][0] * inv; o.y = oacc[i][1] * inv;
        o.z = oacc[i][2] * inv; o.w = oacc[i][3] * inv;
        *reinterpret_cast<float4*>(&orow[tx * 4]) = o;
    }
}

// ---------------------------------------------------------------------------
extern "C" void kernel_launch(void* const* d_in, const int* in_sizes, int n_in,
                              void* d_out, int out_size)
{
    const float* x     = (const float*)d_in[0];
    const float* W_in  = (const float*)d_in[1];
    const float* b_in  = (const float*)d_in[2];
    const float* W_out = (const float*)d_in[3];
    const float* b_out = (const float*)d_in[4];
    float* out = (float*)d_out;

    float* qkv = nullptr;
    float* att = nullptr;
    cudaGetSymbolAddress((void**)&qkv, g_qkv);
    cudaGetSymbolAddress((void**)&att, g_att);

    cudaFuncSetAttribute(attn_kernel,
                         cudaFuncAttributeMaxDynamicSharedMemorySize,
                         ATTN_SMEM_BYTES);

    // 1) QKV projection: [8192,3072] = x @ W_in^T + b_in   (mma.sync bf16-split)
    {
        dim3 grid(N_QKV / GBN, MROWS / GBM);
        gemm_mma_kernel<<<grid, 256>>>(x, W_in, b_in, qkv, MROWS, N_QKV, DE_);
    }
    // 2) Causal flash attention -> att [8192,1024]
    {
        dim3 grid(S_ / AQ, NH_, B_);
        attn_kernel<<<grid, 256, ATTN_SMEM_BYTES>>>(qkv, att);
    }
    // 3) Output projection: out = att @ W_out^T + b_out   (mma.sync bf16-split)
    {
        dim3 grid(DE_ / GBN, MROWS / GBM);
        gemm_mma_kernel<<<grid, 256>>>(att, W_out, b_out, out, MROWS, DE_, DE_);
    }
}

// round 10
// speedup vs baseline: 2.0133x; 1.4717x over previous
#include <cuda_runtime.h>
#include <cuda_bf16.h>
#include <math.h>
#include <stdint.h>

// Problem constants
#define B_   4
#define S_   2048
#define DE_  1024
#define NH_  16
#define DH_  64
#define MROWS (B_ * S_)          // 8192
#define N_QKV (3 * DE_)          // 3072

// Scratch (allocation-free rule: __device__ globals)
__device__ float g_qkv[(size_t)MROWS * N_QKV];   // [8192, 3072]
__device__ float g_att[(size_t)MROWS * DE_];     // [8192, 1024]

// ===========================================================================
// mma.sync helpers (plain PTX, sm_80+ -> HMMA on sm_103)
// ===========================================================================
__device__ __forceinline__ void mma16816(float* d, const uint32_t* a, const uint32_t* b)
{
    asm volatile(
        "mma.sync.aligned.m16n8k16.row.col.f32.bf16.bf16.f32 "
        "{%0,%1,%2,%3}, {%4,%5,%6,%7}, {%8,%9}, {%0,%1,%2,%3};"
        : "+f"(d[0]), "+f"(d[1]), "+f"(d[2]), "+f"(d[3])
        : "r"(a[0]), "r"(a[1]), "r"(a[2]), "r"(a[3]), "r"(b[0]), "r"(b[1]));
}

// pack two fp32 -> bf16x2 (x0 in low half)
__device__ __forceinline__ uint32_t pack_bf16x2(float x0, float x1)
{
    uint32_t r;
    asm("cvt.rn.bf16x2.f32 %0, %1, %2;" : "=r"(r) : "f"(x1), "f"(x0));
    return r;
}
__device__ __forceinline__ float bflo(uint32_t p) { return __uint_as_float(p << 16); }
__device__ __forceinline__ float bfhi(uint32_t p) { return __uint_as_float(p & 0xffff0000u); }

// ===========================================================================
// GEMM: C[M,N] = A[M,K] @ W[N,K]^T + bias[N], fp32 via bf16-split mma.sync.
// (unchanged from R8 — 563us QKV / ~190us out-proj, tensor=45%)
// ===========================================================================
#define WS 20
#define GBM 128
#define GBN 128
#define GBK 32

__global__ __launch_bounds__(256, 2) void gemm_mma_kernel(
    const float* __restrict__ A, const float* __restrict__ W,
    const float* __restrict__ bias, float* __restrict__ C,
    int M, int N, int K)
{
    __shared__ uint32_t sAh[128 * WS], sAl[128 * WS];
    __shared__ uint32_t sWh[128 * WS], sWl[128 * WS];

    const int tid  = threadIdx.x;
    const int lane = tid & 31;
    const int wid  = tid >> 5;
    const int wm   = wid >> 2;
    const int wn   = wid & 3;
    const int bm   = blockIdx.y * GBM;
    const int bn   = blockIdx.x * GBN;

    float acc[4][4][4];
    #pragma unroll
    for (int mi = 0; mi < 4; mi++)
        #pragma unroll
        for (int ni = 0; ni < 4; ni++)
            #pragma unroll
            for (int e = 0; e < 4; e++) acc[mi][ni][e] = 0.f;

    const int lrow = tid >> 1;
    const int lh   = tid & 1;
    const float* Ap = A + (size_t)(bm + lrow) * K + lh * 16;
    const float* Wp = W + (size_t)(bn + lrow) * K + lh * 16;
    const int sw = lrow * WS + lh * 8;

    const int fr = lane >> 2;
    const int fc = lane & 3;

    for (int k0 = 0; k0 < K; k0 += GBK) {
        float av[16], wv[16];
        #pragma unroll
        for (int i = 0; i < 4; i++) {
            *reinterpret_cast<float4*>(&av[4 * i]) =
                *reinterpret_cast<const float4*>(Ap + k0 + 4 * i);
            *reinterpret_cast<float4*>(&wv[4 * i]) =
                *reinterpret_cast<const float4*>(Wp + k0 + 4 * i);
        }

        __syncthreads();

        {
            uint32_t ah[8], al[8], wh[8], wl[8];
            #pragma unroll
            for (int p = 0; p < 8; p++) {
                float x0 = av[2 * p], x1 = av[2 * p + 1];
                uint32_t hp = pack_bf16x2(x0, x1);
                ah[p] = hp;
                al[p] = pack_bf16x2(x0 - bflo(hp), x1 - bfhi(hp));

                float y0 = wv[2 * p], y1 = wv[2 * p + 1];
                uint32_t hq = pack_bf16x2(y0, y1);
                wh[p] = hq;
                wl[p] = pack_bf16x2(y0 - bflo(hq), y1 - bfhi(hq));
            }
            *reinterpret_cast<uint4*>(&sAh[sw])     = make_uint4(ah[0], ah[1], ah[2], ah[3]);
            *reinterpret_cast<uint4*>(&sAh[sw + 4]) = make_uint4(ah[4], ah[5], ah[6], ah[7]);
            *reinterpret_cast<uint4*>(&sAl[sw])     = make_uint4(al[0], al[1], al[2], al[3]);
            *reinterpret_cast<uint4*>(&sAl[sw + 4]) = make_uint4(al[4], al[5], al[6], al[7]);
            *reinterpret_cast<uint4*>(&sWh[sw])     = make_uint4(wh[0], wh[1], wh[2], wh[3]);
            *reinterpret_cast<uint4*>(&sWh[sw + 4]) = make_uint4(wh[4], wh[5], wh[6], wh[7]);
            *reinterpret_cast<uint4*>(&sWl[sw])     = make_uint4(wl[0], wl[1], wl[2], wl[3]);
            *reinterpret_cast<uint4*>(&sWl[sw + 4]) = make_uint4(wl[4], wl[5], wl[6], wl[7]);
        }
        __syncthreads();

        #pragma unroll
        for (int s = 0; s < 2; s++) {
            const int wb = s * 8;
            uint32_t af[4][4], bh[4][2], bl[4][2];

            #pragma unroll
            for (int ni = 0; ni < 4; ni++) {
                const int nb = (wn * 32 + ni * 8 + fr) * WS + wb + fc;
                bh[ni][0] = sWh[nb]; bh[ni][1] = sWh[nb + 4];
                bl[ni][0] = sWl[nb]; bl[ni][1] = sWl[nb + 4];
            }
            #pragma unroll
            for (int mi = 0; mi < 4; mi++) {
                const int ab = (wm * 64 + mi * 16 + fr) * WS + wb + fc;
                af[mi][0] = sAh[ab];           af[mi][1] = sAh[ab + 8 * WS];
                af[mi][2] = sAh[ab + 4];       af[mi][3] = sAh[ab + 8 * WS + 4];
            }
            #pragma unroll
            for (int mi = 0; mi < 4; mi++)
                #pragma unroll
                for (int ni = 0; ni < 4; ni++) {
                    mma16816(acc[mi][ni], af[mi], bh[ni]);
                    mma16816(acc[mi][ni], af[mi], bl[ni]);
                }
            #pragma unroll
            for (int mi = 0; mi < 4; mi++) {
                const int ab = (wm * 64 + mi * 16 + fr) * WS + wb + fc;
                af[mi][0] = sAl[ab];           af[mi][1] = sAl[ab + 8 * WS];
                af[mi][2] = sAl[ab + 4];       af[mi][3] = sAl[ab + 8 * WS + 4];
            }
            #pragma unroll
            for (int mi = 0; mi < 4; mi++)
                #pragma unroll
                for (int ni = 0; ni < 4; ni++)
                    mma16816(acc[mi][ni], af[mi], bh[ni]);
        }
    }

    #pragma unroll
    for (int ni = 0; ni < 4; ni++) {
        const int col = bn + wn * 32 + ni * 8 + fc * 2;
        const float2 bv = *reinterpret_cast<const float2*>(&bias[col]);
        #pragma unroll
        for (int mi = 0; mi < 4; mi++) {
            const int row = bm + wm * 64 + mi * 16 + fr;
            float2 o0, o1;
            o0.x = acc[mi][ni][0] + bv.x; o0.y = acc[mi][ni][1] + bv.y;
            o1.x = acc[mi][ni][2] + bv.x; o1.y = acc[mi][ni][3] + bv.y;
            *reinterpret_cast<float2*>(C + (size_t)row * N + col)       = o0;
            *reinterpret_cast<float2*>(C + (size_t)(row + 8) * N + col) = o1;
        }
    }
}

// ===========================================================================
// Flash attention (causal) on mma.sync, bf16-split for QK^T and PV.
// CTA = 64 q-rows x 64 k-tile, 128 threads (4 warps x 16 q-rows).
// SMEM: Qh/Ql/Kh/Kl [row][d] packed pairs; Vh/Vl transposed [d][k] pairs.
// Row stride 36 words -> all fragment LDS conflict-free.
// P stays in registers (S-fragment layout == A-fragment layout).
// ===========================================================================
#define AST 36
#define ATTN_SMEM_BYTES (6 * 64 * AST * 4)   // 55296

__global__ __launch_bounds__(128) void attn_mma_kernel(
    const float* __restrict__ qkv, float* __restrict__ out)
{
    extern __shared__ uint32_t sm[];
    uint32_t* sQh = sm;
    uint32_t* sQl = sQh + 64 * AST;
    uint32_t* sKh = sQl + 64 * AST;
    uint32_t* sKl = sKh + 64 * AST;
    uint32_t* sVh = sKl + 64 * AST;   // [d][kp]
    uint32_t* sVl = sVh + 64 * AST;

    const int STR = 3 * DE_;
    const int qt = blockIdx.x;
    const int h  = blockIdx.y;
    const int b  = blockIdx.z;

    const float* Qg = qkv + (size_t)b * S_ * STR + h * DH_;
    const float* Kg = Qg + DE_;
    const float* Vg = Qg + 2 * DE_;

    const int tid  = threadIdx.x;
    const int lane = tid & 31;
    const int wid  = tid >> 5;
    const int fr   = lane >> 2;
    const int fc   = lane & 3;

    // ---- load Q tile (rows qt*64..+64), split hi/lo ----
    {
        const int r = tid >> 1, half = tid & 1;
        const float* qrow = Qg + (size_t)(qt * 64 + r) * STR + half * 32;
        uint32_t hb[16], lb[16];
        #pragma unroll
        for (int i = 0; i < 8; i++) {
            float4 v = *reinterpret_cast<const float4*>(qrow + 4 * i);
            uint32_t h0 = pack_bf16x2(v.x, v.y);
            uint32_t h1 = pack_bf16x2(v.z, v.w);
            hb[2 * i]     = h0;
            hb[2 * i + 1] = h1;
            lb[2 * i]     = pack_bf16x2(v.x - bflo(h0), v.y - bfhi(h0));
            lb[2 * i + 1] = pack_bf16x2(v.z - bflo(h1), v.w - bfhi(h1));
        }
        const int base = r * AST + half * 16;
        #pragma unroll
        for (int i = 0; i < 4; i++) {
            *reinterpret_cast<uint4*>(&sQh[base + 4 * i]) =
                make_uint4(hb[4 * i], hb[4 * i + 1], hb[4 * i + 2], hb[4 * i + 3]);
            *reinterpret_cast<uint4*>(&sQl[base + 4 * i]) =
                make_uint4(lb[4 * i], lb[4 * i + 1], lb[4 * i + 2], lb[4 * i + 3]);
        }
    }

    float o[8][4];
    #pragma unroll
    for (int d = 0; d < 8; d++)
        #pragma unroll
        for (int e = 0; e < 4; e++) o[d][e] = 0.f;
    float m0 = -INFINITY, m1 = -INFINITY, l0 = 0.f, l1 = 0.f;

    for (int kt = 0; kt <= qt; kt++) {
        __syncthreads();   // prior-iter fragment reads done (also Q stores, 1st iter)

        // ---- load K tile (split, [k'][d]) ----
        {
            const int r = tid >> 1, half = tid & 1;
            const float* krow = Kg + (size_t)(kt * 64 + r) * STR + half * 32;
            uint32_t hb[16], lb[16];
            #pragma unroll
            for (int i = 0; i < 8; i++) {
                float4 v = *reinterpret_cast<const float4*>(krow + 4 * i);
                uint32_t h0 = pack_bf16x2(v.x, v.y);
                uint32_t h1 = pack_bf16x2(v.z, v.w);
                hb[2 * i]     = h0;
                hb[2 * i + 1] = h1;
                lb[2 * i]     = pack_bf16x2(v.x - bflo(h0), v.y - bfhi(h0));
                lb[2 * i + 1] = pack_bf16x2(v.z - bflo(h1), v.w - bfhi(h1));
            }
            const int base = r * AST + half * 16;
            #pragma unroll
            for (int i = 0; i < 4; i++) {
                *reinterpret_cast<uint4*>(&sKh[base + 4 * i]) =
                    make_uint4(hb[4 * i], hb[4 * i + 1], hb[4 * i + 2], hb[4 * i + 3]);
                *reinterpret_cast<uint4*>(&sKl[base + 4 * i]) =
                    make_uint4(lb[4 * i], lb[4 * i + 1], lb[4 * i + 2], lb[4 * i + 3]);
            }
        }
        // ---- load V tile transposed (split, [d][k-pairs]) ----
        {
            const int kp = tid & 31;           // k-pair 0..31
            const int db = (tid >> 5) * 16;    // d-range base
            const float* v0 = Vg + (size_t)(kt * 64 + 2 * kp) * STR + db;
            const float* v1 = v0 + STR;
            #pragma unroll
            for (int i = 0; i < 4; i++) {
                float4 a = *reinterpret_cast<const float4*>(v0 + 4 * i);
                float4 c = *reinterpret_cast<const float4*>(v1 + 4 * i);
                float ae[4] = {a.x, a.y, a.z, a.w};
                float ce[4] = {c.x, c.y, c.z, c.w};
                #pragma unroll
                for (int e = 0; e < 4; e++) {
                    const int d = db + 4 * i + e;
                    uint32_t hp = pack_bf16x2(ae[e], ce[e]);
                    sVh[d * AST + kp] = hp;
                    sVl[d * AST + kp] = pack_bf16x2(ae[e] - bflo(hp), ce[e] - bfhi(hp));
                }
            }
        }
        __syncthreads();

        // ---- S = Q K^T (3-term split), warp covers 16 q-rows x 64 k-cols ----
        float s[8][4];
        #pragma unroll
        for (int nb = 0; nb < 8; nb++)
            #pragma unroll
            for (int e = 0; e < 4; e++) s[nb][e] = 0.f;

        #pragma unroll
        for (int ks = 0; ks < 4; ks++) {
            uint32_t ah[4], al[4];
            const int ab = (wid * 16 + fr) * AST + ks * 8 + fc;
            ah[0] = sQh[ab];           ah[1] = sQh[ab + 8 * AST];
            ah[2] = sQh[ab + 4];       ah[3] = sQh[ab + 8 * AST + 4];
            al[0] = sQl[ab];           al[1] = sQl[ab + 8 * AST];
            al[2] = sQl[ab + 4];       al[3] = sQl[ab + 8 * AST + 4];
            #pragma unroll
            for (int nb = 0; nb < 8; nb++) {
                const int bb = (nb * 8 + fr) * AST + ks * 8 + fc;
                uint32_t bh[2] = {sKh[bb], sKh[bb + 4]};
                uint32_t bl[2] = {sKl[bb], sKl[bb + 4]};
                mma16816(s[nb], ah, bh);
                mma16816(s[nb], ah, bl);
                mma16816(s[nb], al, bh);
            }
        }

        // ---- scale, causal mask, online softmax (registers + shfl) ----
        const bool diag = (kt == qt);
        const int r0 = wid * 16 + fr;     // local q-row of elems 0,1
        const int r1 = r0 + 8;            // local q-row of elems 2,3
        float mx0 = -INFINITY, mx1 = -INFINITY;
        #pragma unroll
        for (int nb = 0; nb < 8; nb++) {
            const int c0 = nb * 8 + 2 * fc, c1 = c0 + 1;
            float v0 = s[nb][0] * 0.125f, v1 = s[nb][1] * 0.125f;
            float v2 = s[nb][2] * 0.125f, v3 = s[nb][3] * 0.125f;
            if (diag) {
                if (c0 > r0) v0 = -INFINITY;
                if (c1 > r0) v1 = -INFINITY;
                if (c0 > r1) v2 = -INFINITY;
                if (c1 > r1) v3 = -INFINITY;
            }
            s[nb][0] = v0; s[nb][1] = v1; s[nb][2] = v2; s[nb][3] = v3;
            mx0 = fmaxf(mx0, fmaxf(v0, v1));
            mx1 = fmaxf(mx1, fmaxf(v2, v3));
        }
        mx0 = fmaxf(mx0, __shfl_xor_sync(0xffffffffu, mx0, 1));
        mx0 = fmaxf(mx0, __shfl_xor_sync(0xffffffffu, mx0, 2));
        mx1 = fmaxf(mx1, __shfl_xor_sync(0xffffffffu, mx1, 1));
        mx1 = fmaxf(mx1, __shfl_xor_sync(0xffffffffu, mx1, 2));

        const float m0n = fmaxf(m0, mx0);
        const float m1n = fmaxf(m1, mx1);
        const float rs0 = __expf(m0 - m0n);
        const float rs1 = __expf(m1 - m1n);
        m0 = m0n; m1 = m1n;

        float sum0 = 0.f, sum1 = 0.f;
        #pragma unroll
        for (int nb = 0; nb < 8; nb++) {
            float p0 = __expf(s[nb][0] - m0);
            float p1 = __expf(s[nb][1] - m0);
            float p2 = __expf(s[nb][2] - m1);
            float p3 = __expf(s[nb][3] - m1);
            s[nb][0] = p0; s[nb][1] = p1; s[nb][2] = p2; s[nb][3] = p3;
            sum0 += p0 + p1;
            sum1 += p2 + p3;
        }
        sum0 += __shfl_xor_sync(0xffffffffu, sum0, 1);
        sum0 += __shfl_xor_sync(0xffffffffu, sum0, 2);
        sum1 += __shfl_xor_sync(0xffffffffu, sum1, 1);
        sum1 += __shfl_xor_sync(0xffffffffu, sum1, 2);
        l0 = l0 * rs0 + sum0;
        l1 = l1 * rs1 + sum1;

        #pragma unroll
        for (int d = 0; d < 8; d++) {
            o[d][0] *= rs0; o[d][1] *= rs0;
            o[d][2] *= rs1; o[d][3] *= rs1;
        }

        // ---- O += P V (P register-direct; 3-term split) ----
        #pragma unroll
        for (int kc = 0; kc < 4; kc++) {
            uint32_t ph[4], pl[4];
            const float* pA = s[2 * kc];
            const float* pB = s[2 * kc + 1];
            ph[0] = pack_bf16x2(pA[0], pA[1]);
            ph[1] = pack_bf16x2(pA[2], pA[3]);
            ph[2] = pack_bf16x2(pB[0], pB[1]);
            ph[3] = pack_bf16x2(pB[2], pB[3]);
            pl[0] = pack_bf16x2(pA[0] - bflo(ph[0]), pA[1] - bfhi(ph[0]));
            pl[1] = pack_bf16x2(pA[2] - bflo(ph[1]), pA[3] - bfhi(ph[1]));
            pl[2] = pack_bf16x2(pB[0] - bflo(ph[2]), pB[1] - bfhi(ph[2]));
            pl[3] = pack_bf16x2(pB[2] - bflo(ph[3]), pB[3] - bfhi(ph[3]));
            #pragma unroll
            for (int db = 0; db < 8; db++) {
                const int bb = (db * 8 + fr) * AST + kc * 8 + fc;
                uint32_t bh[2] = {sVh[bb], sVh[bb + 4]};
                uint32_t bl[2] = {sVl[bb], sVl[bb + 4]};
                mma16816(o[db], ph, bh);
                mma16816(o[db], ph, bl);
                mma16816(o[db], pl, bh);
            }
        }
    }

    // ---- epilogue ----
    const float inv0 = 1.f / l0;
    const float inv1 = 1.f / l1;
    const int row0 = qt * 64 + wid * 16 + fr;
    float* out0 = out + ((size_t)b * S_ + row0) * DE_ + h * DH_;
    float* out1 = out0 + (size_t)8 * DE_;
    #pragma unroll
    for (int db = 0; db < 8; db++) {
        const int col = db * 8 + 2 * fc;
        float2 w0, w1;
        w0.x = o[db][0] * inv0; w0.y = o[db][1] * inv0;
        w1.x = o[db][2] * inv1; w1.y = o[db][3] * inv1;
        *reinterpret_cast<float2*>(out0 + col) = w0;
        *reinterpret_cast<float2*>(out1 + col) = w1;
    }
}

// ---------------------------------------------------------------------------
extern "C" void kernel_launch(void* const* d_in, const int* in_sizes, int n_in,
                              void* d_out, int out_size)
{
    const float* x     = (const float*)d_in[0];
    const float* W_in  = (const float*)d_in[1];
    const float* b_in  = (const float*)d_in[2];
    const float* W_out = (const float*)d_in[3];
    const float* b_out = (const float*)d_in[4];
    float* out = (float*)d_out;

    float* qkv = nullptr;
    float* att = nullptr;
    cudaGetSymbolAddress((void**)&qkv, g_qkv);
    cudaGetSymbolAddress((void**)&att, g_att);

    cudaFuncSetAttribute(attn_mma_kernel,
                         cudaFuncAttributeMaxDynamicSharedMemorySize,
                         ATTN_SMEM_BYTES);

    // 1) QKV projection: [8192,3072] = x @ W_in^T + b_in   (mma.sync bf16-split)
    {
        dim3 grid(N_QKV / GBN, MROWS / GBM);
        gemm_mma_kernel<<<grid, 256>>>(x, W_in, b_in, qkv, MROWS, N_QKV, DE_);
    }
    // 2) Causal flash attention -> att [8192,1024]  (mma.sync bf16-split)
    {
        dim3 grid(S_ / 64, NH_, B_);
        attn_mma_kernel<<<grid, 128, ATTN_SMEM_BYTES>>>(qkv, att);
    }
    // 3) Output projection: out = att @ W_out^T + b_out   (mma.sync bf16-split)
    {
        dim3 grid(DE_ / GBN, MROWS / GBM);
        gemm_mma_kernel<<<grid, 256>>>(att, W_out, b_out, out, MROWS, DE_, DE_);
    }
}